// round 1
// baseline (speedup 1.0000x reference)
#include <cuda_runtime.h>
#include <cstdint>

// Problem shape (fixed by dataset): x [65536, 1024] f32, m [1024, 1024] f32.
#define K_DIM 1024
#define N_DIM 1024
#define MAX_M 65536

typedef unsigned long long u64;

// Per-row logmap0 scale factors (scratch: __device__ global, no allocation).
__device__ float g_scales[MAX_M];

// ---------------------------------------------------------------------------
// f32x2 packed-math helpers (Blackwell sm_100+; ptxas never emits these from C++)
// ---------------------------------------------------------------------------
__device__ __forceinline__ u64 pk2(float lo, float hi) {
    u64 r;
    asm("mov.b64 %0, {%1, %2};" : "=l"(r) : "f"(lo), "f"(hi));
    return r;
}
__device__ __forceinline__ void upk2(float& lo, float& hi, u64 v) {
    asm("mov.b64 {%0, %1}, %2;" : "=f"(lo), "=f"(hi) : "l"(v));
}
__device__ __forceinline__ void fma2(u64& d, u64 a, u64 b) {
    asm("fma.rn.f32x2 %0, %1, %2, %0;" : "+l"(d) : "l"(a), "l"(b));
}

// ---------------------------------------------------------------------------
// Kernel 1: per-row scale = artanh(clip(||x_row||, 0.99)) / max(||x_row||, 1e-15)
// One block (128 threads) per row; each thread loads 2 float4 (8 floats).
// ---------------------------------------------------------------------------
__global__ void scales_kernel(const float* __restrict__ x) {
    const int row = blockIdx.x;
    const float4* xr = reinterpret_cast<const float4*>(x + (size_t)row * K_DIM);
    float ss = 0.0f;
#pragma unroll
    for (int i = 0; i < 2; i++) {
        float4 v = xr[threadIdx.x + i * 128];
        // nan_to_num
        v.x = (v.x == v.x) ? v.x : 0.0f;
        v.y = (v.y == v.y) ? v.y : 0.0f;
        v.z = (v.z == v.z) ? v.z : 0.0f;
        v.w = (v.w == v.w) ? v.w : 0.0f;
        ss += v.x * v.x + v.y * v.y + v.z * v.z + v.w * v.w;
    }
#pragma unroll
    for (int o = 16; o > 0; o >>= 1) ss += __shfl_down_sync(0xFFFFFFFFu, ss, o);
    __shared__ float wsum[4];
    if ((threadIdx.x & 31) == 0) wsum[threadIdx.x >> 5] = ss;
    __syncthreads();
    if (threadIdx.x == 0) {
        float t = wsum[0] + wsum[1] + wsum[2] + wsum[3];
        float pn = fmaxf(sqrtf(t), 1e-15f);
        // arg = clip(pn, -0.99, 0.99), then artanh's internal clamp to ±(0.99 - 1e-7)
        float arg = fminf(pn, 0.99f);
        arg = fminf(arg, 0.99f - 1e-7f);
        arg = fmaxf(arg, -0.99f + 1e-7f);
        float at = 0.5f * (log1pf(arg) - log1pf(-arg));
        g_scales[row] = at / pn;
    }
}

// ---------------------------------------------------------------------------
// Kernel 2: C[M,N] = clip( (clip(s_r * x, ±50)) @ m^T, ±1000 )
// Classic 128x128x16 shared-memory tile, 256 threads, 8x8 per thread.
// Accumulators packed as f32x2 (doubles fp32 FMA throughput vs FFMA-3reg).
// A and B are both K-major (NT GEMM) -> identical coalesced load paths.
// ---------------------------------------------------------------------------
#define BM 128
#define BN 128
#define BK 16

__global__ __launch_bounds__(256, 2)
void gemm_kernel(const float* __restrict__ A, const float* __restrict__ Bm,
                 float* __restrict__ C) {
    __shared__ float As[BK][BM];
    __shared__ float Bs[BK][BN];

    const int bm = blockIdx.y * BM;
    const int bn = blockIdx.x * BN;
    const int tid = (int)threadIdx.x;

    // Load mapping: 256 threads cover 128 rows x 16 k-floats (8 floats/thread).
    const int lr = tid >> 1;            // 0..127
    const int lc = (tid & 1) << 3;      // 0 or 8
    const float s = g_scales[bm + lr];
    const float* Ap = A + (size_t)(bm + lr) * K_DIM + lc;
    const float* Bp = Bm + (size_t)(bn + lr) * K_DIM + lc;

    const int ty = tid >> 4;            // 0..15  (C row group)
    const int tx = tid & 15;            // 0..15  (C col group)

    u64 acc[8][4];
#pragma unroll
    for (int i = 0; i < 8; i++)
#pragma unroll
        for (int j = 0; j < 4; j++) acc[i][j] = 0ull;  // (+0.f, +0.f)

    for (int k0 = 0; k0 < K_DIM; k0 += BK) {
        float4 a0 = *(const float4*)(Ap + k0);
        float4 a1 = *(const float4*)(Ap + k0 + 4);
        float4 b0 = *(const float4*)(Bp + k0);
        float4 b1 = *(const float4*)(Bp + k0 + 4);

        float av[8] = {a0.x, a0.y, a0.z, a0.w, a1.x, a1.y, a1.z, a1.w};
        float bv[8] = {b0.x, b0.y, b0.z, b0.w, b1.x, b1.y, b1.z, b1.w};
#pragma unroll
        for (int j = 0; j < 8; j++) {
            float v = av[j];
            v = (v == v) ? v : 0.0f;                 // nan_to_num
            v = fminf(fmaxf(v * s, -50.0f), 50.0f);  // x_tan clip
            As[lc + j][lr] = v;
            Bs[lc + j][lr] = bv[j];
        }
        __syncthreads();

#pragma unroll
        for (int k = 0; k < BK; k++) {
            float4 ra0 = *(const float4*)&As[k][ty * 8];
            float4 ra1 = *(const float4*)&As[k][ty * 8 + 4];
            float4 rb0 = *(const float4*)&Bs[k][tx * 8];
            float4 rb1 = *(const float4*)&Bs[k][tx * 8 + 4];

            u64 bp[4] = {pk2(rb0.x, rb0.y), pk2(rb0.z, rb0.w),
                         pk2(rb1.x, rb1.y), pk2(rb1.z, rb1.w)};
            float ra[8] = {ra0.x, ra0.y, ra0.z, ra0.w,
                           ra1.x, ra1.y, ra1.z, ra1.w};
#pragma unroll
            for (int i = 0; i < 8; i++) {
                u64 ad = pk2(ra[i], ra[i]);
                fma2(acc[i][0], ad, bp[0]);
                fma2(acc[i][1], ad, bp[1]);
                fma2(acc[i][2], ad, bp[2]);
                fma2(acc[i][3], ad, bp[3]);
            }
        }
        __syncthreads();
    }

    // Store with mx clip to ±1000.
#pragma unroll
    for (int i = 0; i < 8; i++) {
        float o[8];
#pragma unroll
        for (int jp = 0; jp < 4; jp++) upk2(o[2 * jp], o[2 * jp + 1], acc[i][jp]);
#pragma unroll
        for (int j = 0; j < 8; j++) o[j] = fminf(fmaxf(o[j], -1000.0f), 1000.0f);
        float* Cp = C + (size_t)(bm + ty * 8 + i) * N_DIM + bn + tx * 8;
        *(float4*)(Cp)     = make_float4(o[0], o[1], o[2], o[3]);
        *(float4*)(Cp + 4) = make_float4(o[4], o[5], o[6], o[7]);
    }
}

// ---------------------------------------------------------------------------
// Kernel 3 (in-place on d_out): out = proj(expmap0(mx, 1), 1)
// One block (256 threads) per row; each thread owns one float4.
// ---------------------------------------------------------------------------
__global__ void epilogue_kernel(float* __restrict__ C) {
    const int row = blockIdx.x;
    float4* p = reinterpret_cast<float4*>(C + (size_t)row * N_DIM);
    float4 v = p[threadIdx.x];
    // clip to ±1000 (idempotent with GEMM store clip)
    v.x = fminf(fmaxf(v.x, -1000.0f), 1000.0f);
    v.y = fminf(fmaxf(v.y, -1000.0f), 1000.0f);
    v.z = fminf(fmaxf(v.z, -1000.0f), 1000.0f);
    v.w = fminf(fmaxf(v.w, -1000.0f), 1000.0f);

    float ss = v.x * v.x + v.y * v.y + v.z * v.z + v.w * v.w;
#pragma unroll
    for (int o = 16; o > 0; o >>= 1) ss += __shfl_down_sync(0xFFFFFFFFu, ss, o);
    __shared__ float wsum[8];
    __shared__ float total_s;
    if ((threadIdx.x & 31) == 0) wsum[threadIdx.x >> 5] = ss;
    __syncthreads();
    if (threadIdx.x == 0) {
        float t = 0.0f;
#pragma unroll
        for (int w = 0; w < 8; w++) t += wsum[w];
        total_s = t;
    }
    __syncthreads();

    const float un = fmaxf(sqrtf(total_s), 1e-15f);   // expmap0 u_norm
    const float th = tanhf(un);
    float f = th / un;
    // proj: result norm == |tanh(un)| analytically; max_norm = 1 - 1e-10 -> 1.0f in f32
    const float max_norm = (float)(1.0 - 1e-10);
    const float xn = th;
    if (xn > max_norm) f *= max_norm / fmaxf(xn, 1e-9f);

    v.x *= f; v.y *= f; v.z *= f; v.w *= f;
    p[threadIdx.x] = v;
}

// ---------------------------------------------------------------------------
extern "C" void kernel_launch(void* const* d_in, const int* in_sizes, int n_in,
                              void* d_out, int out_size) {
    const float* x = (const float*)d_in[0];   // [M, 1024]
    const float* m = (const float*)d_in[1];   // [1024, 1024]
    float* out = (float*)d_out;               // [M, 1024] f32

    int M = in_sizes[0] / K_DIM;
    if (M > MAX_M) M = MAX_M;

    scales_kernel<<<M, 128>>>(x);

    dim3 grid(N_DIM / BN, M / BM);
    gemm_kernel<<<grid, 256>>>(x, m, out);

    epilogue_kernel<<<M, 256>>>(out);
}

// round 3
// speedup vs baseline: 2.5579x; 2.5579x over previous
#include <cuda_runtime.h>
#include <cuda_fp16.h>
#include <cstdint>

#define K_DIM 1024
#define N_DIM 1024
#define MAX_M 65536

// ---------------------------------------------------------------------------
// Scratch (device globals — no allocation APIs allowed)
// ---------------------------------------------------------------------------
__device__ __half g_Ahi[(size_t)MAX_M * K_DIM];
__device__ __half g_Alo[(size_t)MAX_M * K_DIM];
__device__ __half g_Bhi[(size_t)N_DIM * K_DIM];
__device__ __half g_Blo[(size_t)N_DIM * K_DIM];

__device__ __forceinline__ uint32_t smem_u32(const void* p) {
    uint32_t a;
    asm("{ .reg .u64 t; cvta.to.shared.u64 t, %1; cvt.u32.u64 %0, t; }"
        : "=r"(a) : "l"(p));
    return a;
}

__device__ __forceinline__ void cp_async16(uint32_t saddr, const void* gaddr) {
    asm volatile("cp.async.cg.shared.global [%0], [%1], 16;"
                 :: "r"(saddr), "l"(gaddr) : "memory");
}

__device__ __forceinline__ void ldsm_x4(uint32_t addr, uint32_t& r0, uint32_t& r1,
                                        uint32_t& r2, uint32_t& r3) {
    asm volatile("ldmatrix.sync.aligned.m8n8.x4.shared.b16 {%0,%1,%2,%3}, [%4];"
                 : "=r"(r0), "=r"(r1), "=r"(r2), "=r"(r3) : "r"(addr));
}

__device__ __forceinline__ void mma16816(float* c, const uint32_t* a,
                                         const uint32_t* b) {
    asm volatile(
        "mma.sync.aligned.m16n8k16.row.col.f32.f16.f16.f32 "
        "{%0,%1,%2,%3}, {%4,%5,%6,%7}, {%8,%9}, {%0,%1,%2,%3};"
        : "+f"(c[0]), "+f"(c[1]), "+f"(c[2]), "+f"(c[3])
        : "r"(a[0]), "r"(a[1]), "r"(a[2]), "r"(a[3]), "r"(b[0]), "r"(b[1]));
}

// ---------------------------------------------------------------------------
// Kernel 1: per-row logmap0 scale fused with fp16 hi/lo split of A.
// One block (256 threads) per row; each thread owns one float4.
// ---------------------------------------------------------------------------
__global__ void convertA_kernel(const float* __restrict__ x) {
    const int row = blockIdx.x;
    const int t = threadIdx.x;
    const float4* xr = reinterpret_cast<const float4*>(x + ((size_t)row << 10));
    float4 v = xr[t];
    v.x = (v.x == v.x) ? v.x : 0.0f;
    v.y = (v.y == v.y) ? v.y : 0.0f;
    v.z = (v.z == v.z) ? v.z : 0.0f;
    v.w = (v.w == v.w) ? v.w : 0.0f;

    float ss = v.x * v.x + v.y * v.y + v.z * v.z + v.w * v.w;
#pragma unroll
    for (int o = 16; o > 0; o >>= 1) ss += __shfl_down_sync(0xFFFFFFFFu, ss, o);
    __shared__ float ws[8];
    __shared__ float s_scale;
    if ((t & 31) == 0) ws[t >> 5] = ss;
    __syncthreads();
    if (t == 0) {
        float tt = 0.0f;
#pragma unroll
        for (int w = 0; w < 8; w++) tt += ws[w];
        float pn = fmaxf(sqrtf(tt), 1e-15f);
        float arg = fminf(pn, 0.99f - 1e-7f);
        arg = fmaxf(arg, -0.99f + 1e-7f);
        float at = 0.5f * (log1pf(arg) - log1pf(-arg));
        s_scale = at / pn;
    }
    __syncthreads();
    const float s = s_scale;

    float a[4] = {v.x, v.y, v.z, v.w};
    __half hi[4], lo[4];
#pragma unroll
    for (int i = 0; i < 4; i++) {
        float w = fminf(fmaxf(a[i] * s, -50.0f), 50.0f);
        hi[i] = __float2half_rn(w);
        lo[i] = __float2half_rn(w - __half2float(hi[i]));
    }
    __half2* ph = reinterpret_cast<__half2*>(g_Ahi + ((size_t)row << 10));
    __half2* pl = reinterpret_cast<__half2*>(g_Alo + ((size_t)row << 10));
    ph[2 * t]     = __halves2half2(hi[0], hi[1]);
    ph[2 * t + 1] = __halves2half2(hi[2], hi[3]);
    pl[2 * t]     = __halves2half2(lo[0], lo[1]);
    pl[2 * t + 1] = __halves2half2(lo[2], lo[3]);
}

// ---------------------------------------------------------------------------
// Kernel 2: fp16 hi/lo split of m (1024x1024).
// ---------------------------------------------------------------------------
__global__ void convertB_kernel(const float* __restrict__ m) {
    const size_t i = (size_t)blockIdx.x * 256 + threadIdx.x;  // 262144 float4s
    float4 v = reinterpret_cast<const float4*>(m)[i];
    float a[4] = {v.x, v.y, v.z, v.w};
    __half hi[4], lo[4];
#pragma unroll
    for (int j = 0; j < 4; j++) {
        hi[j] = __float2half_rn(a[j]);
        lo[j] = __float2half_rn(a[j] - __half2float(hi[j]));
    }
    __half2* ph = reinterpret_cast<__half2*>(g_Bhi);
    __half2* pl = reinterpret_cast<__half2*>(g_Blo);
    ph[2 * i]     = __halves2half2(hi[0], hi[1]);
    ph[2 * i + 1] = __halves2half2(hi[2], hi[3]);
    pl[2 * i]     = __halves2half2(lo[0], lo[1]);
    pl[2 * i + 1] = __halves2half2(lo[2], lo[3]);
}

// ---------------------------------------------------------------------------
// Kernel 3: HMMA GEMM via mma.sync m16n8k16 (fp16 in, fp32 acc), 3-pass split.
// CTA tile 128x128, BK=64, 8 warps (4m x 2n), double-buffered cp.async SMEM.
// SMEM per stage: {Ahi, Alo, Bhi, Blo} x (128 rows x 128B, SW128 swizzle).
// ---------------------------------------------------------------------------
#define TILE_B 16384
#define STAGE_B (4 * TILE_B)
#define SMEM_TOTAL (2 * STAGE_B)

__global__ __launch_bounds__(256, 1) void gemm_hmma(float* __restrict__ C) {
    extern __shared__ char smem[];
    const uint32_t sb = smem_u32(smem);
    const int tid = threadIdx.x;
    const int wid = tid >> 5, lid = tid & 31;
    const int wm = wid & 3, wn = wid >> 2;        // warp grid 4(m) x 2(n)
    const int bm = blockIdx.y << 7, bn = blockIdx.x << 7;

    const __half* gsrc[4] = {g_Ahi, g_Alo, g_Bhi, g_Blo};
    const int rbase[4] = {bm, bm, bn, bn};

    auto load_stage = [&](int st, int k0) {
#pragma unroll
        for (int t = 0; t < 4; t++) {
            const __half* g = gsrc[t];
            const uint32_t sdst = sb + st * STAGE_B + t * TILE_B;
#pragma unroll
            for (int i = 0; i < 4; i++) {
                int idx = tid + (i << 8);           // 0..1023
                int r = idx >> 3;                   // 0..127
                int c16 = idx & 7;                  // 16B chunk in row
                uint32_t boff = (uint32_t)((r << 7) + (c16 << 4));
                uint32_t sw = boff ^ ((boff >> 3) & 0x70);
                cp_async16(sdst + sw,
                           g + ((size_t)(rbase[t] + r) << 10) + k0 + (c16 << 3));
            }
        }
        asm volatile("cp.async.commit_group;" ::: "memory");
    };

    // ldmatrix lane addressing: row = base + (lid & 15); kb = kk*32 + (lid>>4)*16
    const int lr = lid & 15;
    const int khalf = (lid >> 4) << 4;
    // A rows for 2 m-frags; B rows for 4 n-frag-pairs
    uint32_t rA[2], xA[2], rB[4], xB[4];
#pragma unroll
    for (int i = 0; i < 2; i++) {
        int r = wm * 32 + i * 16 + lr;
        rA[i] = (uint32_t)(r << 7);
        xA[i] = (uint32_t)((r & 7) << 4);
    }
#pragma unroll
    for (int j = 0; j < 4; j++) {
        int r = wn * 64 + j * 16 + lr;
        rB[j] = (uint32_t)(r << 7);
        xB[j] = (uint32_t)((r & 7) << 4);
    }

    float acc[2][8][4];
#pragma unroll
    for (int i = 0; i < 2; i++)
#pragma unroll
        for (int j = 0; j < 8; j++)
#pragma unroll
            for (int q = 0; q < 4; q++) acc[i][j][q] = 0.0f;

    load_stage(0, 0);

    for (int c = 0; c < 16; ++c) {
        asm volatile("cp.async.wait_group 0;" ::: "memory");
        __syncthreads();
        if (c < 15) load_stage((c + 1) & 1, (c + 1) << 6);

        const uint32_t stb = sb + (c & 1) * STAGE_B;
        const uint32_t tAh = stb, tAl = stb + TILE_B;
        const uint32_t tBh = stb + 2 * TILE_B, tBl = stb + 3 * TILE_B;

#pragma unroll
        for (int kk = 0; kk < 4; kk++) {
            const uint32_t kb = (uint32_t)(kk * 32) + khalf;

            uint32_t ah[2][4], al[2][4];
#pragma unroll
            for (int i = 0; i < 2; i++) {
                uint32_t off = rA[i] + (kb ^ xA[i]);
                ldsm_x4(tAh + off, ah[i][0], ah[i][1], ah[i][2], ah[i][3]);
                ldsm_x4(tAl + off, al[i][0], al[i][1], al[i][2], al[i][3]);
            }
            uint32_t bh[8][2], bl[8][2];
#pragma unroll
            for (int j = 0; j < 4; j++) {
                uint32_t off = rB[j] + (kb ^ xB[j]);
                uint32_t r0, r1, r2, r3;
                ldsm_x4(tBh + off, r0, r1, r2, r3);
                bh[2 * j][0] = r0; bh[2 * j + 1][0] = r1;
                bh[2 * j][1] = r2; bh[2 * j + 1][1] = r3;
                ldsm_x4(tBl + off, r0, r1, r2, r3);
                bl[2 * j][0] = r0; bl[2 * j + 1][0] = r1;
                bl[2 * j][1] = r2; bl[2 * j + 1][1] = r3;
            }
#pragma unroll
            for (int i = 0; i < 2; i++)
#pragma unroll
                for (int j = 0; j < 8; j++) mma16816(acc[i][j], ah[i], bh[j]);
#pragma unroll
            for (int i = 0; i < 2; i++)
#pragma unroll
                for (int j = 0; j < 8; j++) mma16816(acc[i][j], ah[i], bl[j]);
#pragma unroll
            for (int i = 0; i < 2; i++)
#pragma unroll
                for (int j = 0; j < 8; j++) mma16816(acc[i][j], al[i], bh[j]);
        }
        __syncthreads();
    }

    // Store with mx clip to ±1000.
    const int r0 = bm + wm * 32 + (lid >> 2);
    const int c0 = bn + wn * 64 + ((lid & 3) << 1);
#pragma unroll
    for (int i = 0; i < 2; i++) {
#pragma unroll
        for (int j = 0; j < 8; j++) {
            float2 p0, p1;
            p0.x = fminf(fmaxf(acc[i][j][0], -1000.0f), 1000.0f);
            p0.y = fminf(fmaxf(acc[i][j][1], -1000.0f), 1000.0f);
            p1.x = fminf(fmaxf(acc[i][j][2], -1000.0f), 1000.0f);
            p1.y = fminf(fmaxf(acc[i][j][3], -1000.0f), 1000.0f);
            size_t base = ((size_t)(r0 + i * 16) << 10) + c0 + j * 8;
            *reinterpret_cast<float2*>(C + base) = p0;
            *reinterpret_cast<float2*>(C + base + (8 << 10)) = p1;
        }
    }
}

// ---------------------------------------------------------------------------
// Kernel 4 (in-place): out = proj(expmap0(mx, 1), 1)
// ---------------------------------------------------------------------------
__global__ void epilogue_kernel(float* __restrict__ C) {
    const int row = blockIdx.x;
    float4* p = reinterpret_cast<float4*>(C + ((size_t)row << 10));
    float4 v = p[threadIdx.x];

    float ss = v.x * v.x + v.y * v.y + v.z * v.z + v.w * v.w;
#pragma unroll
    for (int o = 16; o > 0; o >>= 1) ss += __shfl_down_sync(0xFFFFFFFFu, ss, o);
    __shared__ float wsum[8];
    __shared__ float total_s;
    if ((threadIdx.x & 31) == 0) wsum[threadIdx.x >> 5] = ss;
    __syncthreads();
    if (threadIdx.x == 0) {
        float t = 0.0f;
#pragma unroll
        for (int w = 0; w < 8; w++) t += wsum[w];
        total_s = t;
    }
    __syncthreads();

    const float un = fmaxf(sqrtf(total_s), 1e-15f);
    const float th = tanhf(un);
    float f = th / un;
    const float max_norm = (float)(1.0 - 1e-10);
    if (th > max_norm) f *= max_norm / fmaxf(th, 1e-9f);

    v.x *= f; v.y *= f; v.z *= f; v.w *= f;
    p[threadIdx.x] = v;
}

// ---------------------------------------------------------------------------
extern "C" void kernel_launch(void* const* d_in, const int* in_sizes, int n_in,
                              void* d_out, int out_size) {
    const float* x = (const float*)d_in[0];   // [M, 1024]
    const float* m = (const float*)d_in[1];   // [1024, 1024]
    float* out = (float*)d_out;               // [M, 1024] f32

    int M = in_sizes[0] / K_DIM;
    if (M > MAX_M) M = MAX_M;

    cudaFuncSetAttribute(gemm_hmma, cudaFuncAttributeMaxDynamicSharedMemorySize,
                         SMEM_TOTAL);

    convertA_kernel<<<M, 256>>>(x);
    convertB_kernel<<<1024, 256>>>(m);

    dim3 grid(N_DIM / 128, M / 128);
    gemm_hmma<<<grid, 256, SMEM_TOTAL>>>(out);

    epilogue_kernel<<<M, 256>>>(out);
}

// round 4
// speedup vs baseline: 5.9102x; 2.3106x over previous
#include <cuda_runtime.h>
#include <cuda_fp16.h>
#include <cstdint>

#define K_DIM 1024
#define N_DIM 1024
#define MAX_M 65536

// ---------------------------------------------------------------------------
// Scratch (device globals — no allocation APIs allowed)
// ---------------------------------------------------------------------------
__device__ __half g_A[(size_t)MAX_M * K_DIM];
__device__ __half g_B[(size_t)N_DIM * K_DIM];

__device__ __forceinline__ uint32_t smem_u32(const void* p) {
    uint32_t a;
    asm("{ .reg .u64 t; cvta.to.shared.u64 t, %1; cvt.u32.u64 %0, t; }"
        : "=r"(a) : "l"(p));
    return a;
}

__device__ __forceinline__ void cp_async16(uint32_t saddr, const void* gaddr) {
    asm volatile("cp.async.cg.shared.global [%0], [%1], 16;"
                 :: "r"(saddr), "l"(gaddr) : "memory");
}

__device__ __forceinline__ void ldsm_x4(uint32_t addr, uint32_t& r0, uint32_t& r1,
                                        uint32_t& r2, uint32_t& r3) {
    asm volatile("ldmatrix.sync.aligned.m8n8.x4.shared.b16 {%0,%1,%2,%3}, [%4];"
                 : "=r"(r0), "=r"(r1), "=r"(r2), "=r"(r3) : "r"(addr));
}

__device__ __forceinline__ void mma16816(float* c, const uint32_t* a,
                                         const uint32_t* b) {
    asm volatile(
        "mma.sync.aligned.m16n8k16.row.col.f32.f16.f16.f32 "
        "{%0,%1,%2,%3}, {%4,%5,%6,%7}, {%8,%9}, {%0,%1,%2,%3};"
        : "+f"(c[0]), "+f"(c[1]), "+f"(c[2]), "+f"(c[3])
        : "r"(a[0]), "r"(a[1]), "r"(a[2]), "r"(a[3]), "r"(b[0]), "r"(b[1]));
}

// ---------------------------------------------------------------------------
// Kernel 1: per-row logmap0 scale fused with fp16 convert of A.
// One block (256 threads) per row; each thread owns one float4.
// ---------------------------------------------------------------------------
__global__ void convertA_kernel(const float* __restrict__ x) {
    const int row = blockIdx.x;
    const int t = threadIdx.x;
    const float4* xr = reinterpret_cast<const float4*>(x + ((size_t)row << 10));
    float4 v = xr[t];
    v.x = (v.x == v.x) ? v.x : 0.0f;
    v.y = (v.y == v.y) ? v.y : 0.0f;
    v.z = (v.z == v.z) ? v.z : 0.0f;
    v.w = (v.w == v.w) ? v.w : 0.0f;

    float ss = v.x * v.x + v.y * v.y + v.z * v.z + v.w * v.w;
#pragma unroll
    for (int o = 16; o > 0; o >>= 1) ss += __shfl_down_sync(0xFFFFFFFFu, ss, o);
    __shared__ float ws[8];
    __shared__ float s_scale;
    if ((t & 31) == 0) ws[t >> 5] = ss;
    __syncthreads();
    if (t == 0) {
        float tt = 0.0f;
#pragma unroll
        for (int w = 0; w < 8; w++) tt += ws[w];
        float pn = fmaxf(sqrtf(tt), 1e-15f);
        float arg = fminf(pn, 0.99f - 1e-7f);
        arg = fmaxf(arg, -0.99f + 1e-7f);
        float at = 0.5f * (log1pf(arg) - log1pf(-arg));
        s_scale = at / pn;
    }
    __syncthreads();
    const float s = s_scale;

    float a[4] = {v.x, v.y, v.z, v.w};
    __half h[4];
#pragma unroll
    for (int i = 0; i < 4; i++) {
        float w = fminf(fmaxf(a[i] * s, -50.0f), 50.0f);
        h[i] = __float2half_rn(w);
    }
    __half2* ph = reinterpret_cast<__half2*>(g_A + ((size_t)row << 10));
    ph[2 * t]     = __halves2half2(h[0], h[1]);
    ph[2 * t + 1] = __halves2half2(h[2], h[3]);
}

// ---------------------------------------------------------------------------
// Kernel 2: fp16 convert of m (1024x1024).
// ---------------------------------------------------------------------------
__global__ void convertB_kernel(const float* __restrict__ m) {
    const size_t i = (size_t)blockIdx.x * 256 + threadIdx.x;  // 262144 float4s
    float4 v = reinterpret_cast<const float4*>(m)[i];
    __half2* ph = reinterpret_cast<__half2*>(g_B);
    ph[2 * i]     = __halves2half2(__float2half_rn(v.x), __float2half_rn(v.y));
    ph[2 * i + 1] = __halves2half2(__float2half_rn(v.z), __float2half_rn(v.w));
}

// ---------------------------------------------------------------------------
// Kernel 3: single-pass fp16 HMMA GEMM (fp32 accumulate).
// CTA tile 128x128, BK=64, 8 warps (4m x 2n). 3-stage cp.async pipeline,
// 32 KB/stage (A tile 16K + B tile 16K, SW128 swizzle), 2 CTAs/SM.
// ---------------------------------------------------------------------------
#define TILE_B 16384
#define STAGE_B (2 * TILE_B)
#define NSTAGE 3
#define SMEM_TOTAL (NSTAGE * STAGE_B)   // 96 KB

__global__ __launch_bounds__(256, 2) void gemm_hmma(float* __restrict__ C) {
    extern __shared__ char smem[];
    const uint32_t sb = smem_u32(smem);
    const int tid = threadIdx.x;
    const int wid = tid >> 5, lid = tid & 31;
    const int wm = wid & 3, wn = wid >> 2;        // warp grid 4(m) x 2(n)
    const int bm = blockIdx.y << 7, bn = blockIdx.x << 7;

    auto load_stage = [&](int st, int k0) {
        const uint32_t sbase = sb + st * STAGE_B;
#pragma unroll
        for (int t = 0; t < 2; t++) {
            const __half* g = t ? g_B : g_A;
            const int rb = t ? bn : bm;
            const uint32_t sdst = sbase + t * TILE_B;
#pragma unroll
            for (int i = 0; i < 4; i++) {
                int idx = tid + (i << 8);           // 0..1023
                int r = idx >> 3;                   // 0..127
                int c16 = idx & 7;                  // 16B chunk in row
                uint32_t boff = (uint32_t)((r << 7) + (c16 << 4));
                uint32_t sw = boff ^ ((boff >> 3) & 0x70);
                cp_async16(sdst + sw,
                           g + ((size_t)(rb + r) << 10) + k0 + (c16 << 3));
            }
        }
        asm volatile("cp.async.commit_group;" ::: "memory");
    };

    // ldmatrix lane addressing (proven in round 3): row = base + (lid&15),
    // k-halves selected by lid>>4.
    const int lr = lid & 15;
    const uint32_t khalf = (uint32_t)((lid >> 4) << 4);
    uint32_t rA[2], xA[2], rB[4], xB[4];
#pragma unroll
    for (int i = 0; i < 2; i++) {
        int r = wm * 32 + i * 16 + lr;
        rA[i] = (uint32_t)(r << 7);
        xA[i] = (uint32_t)((r & 7) << 4);
    }
#pragma unroll
    for (int j = 0; j < 4; j++) {
        int r = wn * 64 + j * 16 + lr;
        rB[j] = (uint32_t)(r << 7);
        xB[j] = (uint32_t)((r & 7) << 4);
    }

    float acc[2][8][4];
#pragma unroll
    for (int i = 0; i < 2; i++)
#pragma unroll
        for (int j = 0; j < 8; j++)
#pragma unroll
            for (int q = 0; q < 4; q++) acc[i][j][q] = 0.0f;

    load_stage(0, 0);
    load_stage(1, 64);

    int st = 0;                         // stage of chunk c
    for (int c = 0; c < 16; ++c) {
        if (c < 15) {
            asm volatile("cp.async.wait_group 1;" ::: "memory");
        } else {
            asm volatile("cp.async.wait_group 0;" ::: "memory");
        }
        __syncthreads();
        if (c + 2 < 16) {
            int st2 = st + 2; if (st2 >= NSTAGE) st2 -= NSTAGE;
            load_stage(st2, (c + 2) << 6);
        }

        const uint32_t stb = sb + st * STAGE_B;
        const uint32_t tA = stb, tB = stb + TILE_B;

#pragma unroll
        for (int kk = 0; kk < 4; kk++) {
            const uint32_t kb = (uint32_t)(kk * 32) + khalf;

            uint32_t a[2][4];
#pragma unroll
            for (int i = 0; i < 2; i++)
                ldsm_x4(tA + rA[i] + (kb ^ xA[i]),
                        a[i][0], a[i][1], a[i][2], a[i][3]);
            uint32_t b[8][2];
#pragma unroll
            for (int j = 0; j < 4; j++) {
                uint32_t r0, r1, r2, r3;
                ldsm_x4(tB + rB[j] + (kb ^ xB[j]), r0, r1, r2, r3);
                b[2 * j][0] = r0; b[2 * j + 1][0] = r1;
                b[2 * j][1] = r2; b[2 * j + 1][1] = r3;
            }
#pragma unroll
            for (int i = 0; i < 2; i++)
#pragma unroll
                for (int j = 0; j < 8; j++) mma16816(acc[i][j], a[i], b[j]);
        }

        st = st + 1; if (st >= NSTAGE) st = 0;
    }

    // Store with mx clip to ±1000.
    const int r0 = bm + wm * 32 + (lid >> 2);
    const int c0 = bn + wn * 64 + ((lid & 3) << 1);
#pragma unroll
    for (int i = 0; i < 2; i++) {
#pragma unroll
        for (int j = 0; j < 8; j++) {
            float2 p0, p1;
            p0.x = fminf(fmaxf(acc[i][j][0], -1000.0f), 1000.0f);
            p0.y = fminf(fmaxf(acc[i][j][1], -1000.0f), 1000.0f);
            p1.x = fminf(fmaxf(acc[i][j][2], -1000.0f), 1000.0f);
            p1.y = fminf(fmaxf(acc[i][j][3], -1000.0f), 1000.0f);
            size_t base = ((size_t)(r0 + i * 16) << 10) + c0 + j * 8;
            *reinterpret_cast<float2*>(C + base) = p0;
            *reinterpret_cast<float2*>(C + base + (8 << 10)) = p1;
        }
    }
}

// ---------------------------------------------------------------------------
// Kernel 4 (in-place): out = proj(expmap0(mx, 1), 1)
// ---------------------------------------------------------------------------
__global__ void epilogue_kernel(float* __restrict__ C) {
    const int row = blockIdx.x;
    float4* p = reinterpret_cast<float4*>(C + ((size_t)row << 10));
    float4 v = p[threadIdx.x];

    float ss = v.x * v.x + v.y * v.y + v.z * v.z + v.w * v.w;
#pragma unroll
    for (int o = 16; o > 0; o >>= 1) ss += __shfl_down_sync(0xFFFFFFFFu, ss, o);
    __shared__ float wsum[8];
    __shared__ float total_s;
    if ((threadIdx.x & 31) == 0) wsum[threadIdx.x >> 5] = ss;
    __syncthreads();
    if (threadIdx.x == 0) {
        float t = 0.0f;
#pragma unroll
        for (int w = 0; w < 8; w++) t += wsum[w];
        total_s = t;
    }
    __syncthreads();

    const float un = fmaxf(sqrtf(total_s), 1e-15f);
    const float th = tanhf(un);
    float f = th / un;
    const float max_norm = (float)(1.0 - 1e-10);
    if (th > max_norm) f *= max_norm / fmaxf(th, 1e-9f);

    v.x *= f; v.y *= f; v.z *= f; v.w *= f;
    p[threadIdx.x] = v;
}

// ---------------------------------------------------------------------------
extern "C" void kernel_launch(void* const* d_in, const int* in_sizes, int n_in,
                              void* d_out, int out_size) {
    const float* x = (const float*)d_in[0];   // [M, 1024]
    const float* m = (const float*)d_in[1];   // [1024, 1024]
    float* out = (float*)d_out;               // [M, 1024] f32

    int M = in_sizes[0] / K_DIM;
    if (M > MAX_M) M = MAX_M;

    cudaFuncSetAttribute(gemm_hmma, cudaFuncAttributeMaxDynamicSharedMemorySize,
                         SMEM_TOTAL);

    convertA_kernel<<<M, 256>>>(x);
    convertB_kernel<<<1024, 256>>>(m);

    dim3 grid(N_DIM / 128, M / 128);
    gemm_hmma<<<grid, 256, SMEM_TOTAL>>>(out);

    epilogue_kernel<<<M, 256>>>(out);
}